// round 1
// baseline (speedup 1.0000x reference)
#include <cuda_runtime.h>
#include <math.h>

#define BATCH 256
#define NA    32
#define OBS   128
#define ACT   8
#define DK    128
#define DV    128
#define DH    64
#define DO    8
#define S1    129   // padded stride for 128-wide rows (conflict-free column access)
#define S2    65    // padded stride for 64-wide rows

// SMEM layout (floats)
#define OFF_STATES 0
#define OFF_Q      (OFF_STATES + NA*S1)
#define OFF_K      (OFF_Q + NA*S1)
#define OFF_AVA    (OFF_K + NA*S1)
#define OFF_DIFF   (OFF_AVA + NA*S1)
#define OFF_W      (OFF_DIFF + NA*S1)
#define OFF_BW1    (OFF_W + NA*NA)
#define OFF_DW1    (OFF_BW1 + NA*S2)
#define OFF_ACT    (OFF_DW1 + NA*S2)
#define OFF_POL    (OFF_ACT + NA*ACT)
#define OFF_W2     (OFF_POL + NA*ACT)
#define SMEM_FLOATS (OFF_W2 + DH*DO)
#define SMEM_BYTES  (SMEM_FLOATS * 4)

__global__ __launch_bounds__(256, 2)
void critic_kernel(const float* __restrict__ states,
                   const float* __restrict__ policies,
                   const float* __restrict__ actions,
                   const float* __restrict__ Wk,
                   const float* __restrict__ Wq,
                   const float* __restrict__ Wv,
                   const float* __restrict__ W1,
                   const float* __restrict__ W2,
                   float* __restrict__ value_out,
                   float* __restrict__ weight_out)
{
    extern __shared__ float sm[];
    float* s_states = sm + OFF_STATES;
    float* s_q      = sm + OFF_Q;      // reused as s_base after scores
    float* s_k      = sm + OFF_K;
    float* s_avA    = sm + OFF_AVA;
    float* s_diff   = sm + OFF_DIFF;
    float* s_w      = sm + OFF_W;
    float* s_bW1    = sm + OFF_BW1;
    float* s_dW1    = sm + OFF_DW1;
    float* s_act    = sm + OFF_ACT;
    float* s_pol    = sm + OFF_POL;
    float* s_W2     = sm + OFF_W2;

    const int b   = blockIdx.x;
    const int tid = threadIdx.x;
    const float* st_b = states + (size_t)b * NA * OBS;

    // ---- stage inputs ----
    for (int idx = tid; idx < NA*OBS; idx += 256) {
        int i = idx >> 7, d = idx & 127;
        s_states[i*S1 + d] = st_b[idx];
    }
    for (int idx = tid; idx < NA*ACT; idx += 256) {
        s_act[idx] = actions [(size_t)b*NA*ACT + idx];
        s_pol[idx] = policies[(size_t)b*NA*ACT + idx];
    }
    for (int idx = tid; idx < DH*DO; idx += 256) s_W2[idx] = W2[idx];
    __syncthreads();

    // ---- q = states@Wq, k = states@Wk (each thread: one d, 16 rows) ----
    {
        const int d  = tid & 127;
        const int i0 = (tid >> 7) * 16;
        float accq[16], acck[16];
        #pragma unroll
        for (int r = 0; r < 16; ++r) { accq[r] = 0.f; acck[r] = 0.f; }
        #pragma unroll 4
        for (int kk = 0; kk < OBS; ++kk) {
            float wq = Wq[kk*DK + d];
            float wk = Wk[kk*DK + d];
            #pragma unroll
            for (int r = 0; r < 16; ++r) {
                float s = s_states[(i0+r)*S1 + kk];
                accq[r] = fmaf(s, wq, accq[r]);
                acck[r] = fmaf(s, wk, acck[r]);
            }
        }
        #pragma unroll
        for (int r = 0; r < 16; ++r) {
            s_q[(i0+r)*S1 + d] = accq[r];
            s_k[(i0+r)*S1 + d] = acck[r];
        }
    }
    __syncthreads();

    // ---- scores (2x2 register tile per thread) ----
    {
        const int i0 = (tid >> 4) * 2;
        const int j0 = (tid & 15) * 2;
        float a00 = 0.f, a01 = 0.f, a10 = 0.f, a11 = 0.f;
        #pragma unroll 4
        for (int kk = 0; kk < DK; ++kk) {
            float q0 = s_q[i0*S1 + kk],     q1 = s_q[(i0+1)*S1 + kk];
            float k0 = s_k[j0*S1 + kk],     k1 = s_k[(j0+1)*S1 + kk];
            a00 = fmaf(q0, k0, a00);  a01 = fmaf(q0, k1, a01);
            a10 = fmaf(q1, k0, a10);  a11 = fmaf(q1, k1, a11);
        }
        const float sc = 0.08838834764831845f;  // 1/sqrt(128)
        s_w[i0*NA + j0]       = a00 * sc;
        s_w[i0*NA + j0 + 1]   = a01 * sc;
        s_w[(i0+1)*NA + j0]   = a10 * sc;
        s_w[(i0+1)*NA + j0+1] = a11 * sc;
    }
    __syncthreads();

    // ---- softmax over j, one row per thread ----
    if (tid < NA) {
        float* row = s_w + tid * NA;
        float m = row[0];
        #pragma unroll
        for (int j = 1; j < NA; ++j) m = fmaxf(m, row[j]);
        float sum = 0.f;
        #pragma unroll
        for (int j = 0; j < NA; ++j) { float e = expf(row[j] - m); row[j] = e; sum += e; }
        float inv = 1.f / sum;
        #pragma unroll
        for (int j = 0; j < NA; ++j) row[j] *= inv;
    }
    __syncthreads();

    // write attention weights output
    for (int idx = tid; idx < NA*NA; idx += 256)
        weight_out[(size_t)b*NA*NA + idx] = s_w[idx];

    // ---- avA = tanh(obs_actions@Wv), diff = tanh(obs_policy@Wv) - avA ----
    // states part of the 136-dot is shared between both.
    {
        const int d  = tid & 127;
        const int j0 = (tid >> 7) * 16;
        float acc[16];
        #pragma unroll
        for (int r = 0; r < 16; ++r) acc[r] = 0.f;
        #pragma unroll 4
        for (int kk = 0; kk < OBS; ++kk) {
            float wv = Wv[kk*DV + d];
            #pragma unroll
            for (int r = 0; r < 16; ++r)
                acc[r] = fmaf(s_states[(j0+r)*S1 + kk], wv, acc[r]);
        }
        float accA[16], accP[16];
        #pragma unroll
        for (int r = 0; r < 16; ++r) { accA[r] = acc[r]; accP[r] = acc[r]; }
        #pragma unroll
        for (int kk = 0; kk < ACT; ++kk) {
            float wv = Wv[(OBS+kk)*DV + d];
            #pragma unroll
            for (int r = 0; r < 16; ++r) {
                accA[r] = fmaf(s_act[(j0+r)*ACT + kk], wv, accA[r]);
                accP[r] = fmaf(s_pol[(j0+r)*ACT + kk], wv, accP[r]);
            }
        }
        #pragma unroll
        for (int r = 0; r < 16; ++r) {
            float tA = tanhf(accA[r]);
            float tP = tanhf(accP[r]);
            s_avA [(j0+r)*S1 + d] = tA;
            s_diff[(j0+r)*S1 + d] = tP - tA;
        }
    }
    __syncthreads();

    // ---- base = weight @ avA  (into old q region) ----
    float* s_base = s_q;
    {
        const int d  = tid & 127;
        const int a0 = (tid >> 7) * 16;
        float acc[16];
        #pragma unroll
        for (int r = 0; r < 16; ++r) acc[r] = 0.f;
        #pragma unroll
        for (int j = 0; j < NA; ++j) {
            float av = s_avA[j*S1 + d];
            #pragma unroll
            for (int r = 0; r < 16; ++r)
                acc[r] = fmaf(s_w[(a0+r)*NA + j], av, acc[r]);
        }
        #pragma unroll
        for (int r = 0; r < 16; ++r)
            s_base[(a0+r)*S1 + d] = acc[r];
    }
    __syncthreads();

    // ---- baseW1 = base@W1, diffW1 = diff@W1 (shared W1 loads) ----
    {
        const int a  = tid & 31;
        const int h0 = (tid >> 5) * 8;
        float accB[8], accD[8];
        #pragma unroll
        for (int r = 0; r < 8; ++r) { accB[r] = 0.f; accD[r] = 0.f; }
        #pragma unroll 2
        for (int d = 0; d < DV; ++d) {
            float bb = s_base[a*S1 + d];
            float dd = s_diff[a*S1 + d];
            float4 w1a = *reinterpret_cast<const float4*>(&W1[d*DH + h0]);
            float4 w1b = *reinterpret_cast<const float4*>(&W1[d*DH + h0 + 4]);
            float w1[8] = {w1a.x, w1a.y, w1a.z, w1a.w, w1b.x, w1b.y, w1b.z, w1b.w};
            #pragma unroll
            for (int r = 0; r < 8; ++r) {
                accB[r] = fmaf(bb, w1[r], accB[r]);
                accD[r] = fmaf(dd, w1[r], accD[r]);
            }
        }
        #pragma unroll
        for (int r = 0; r < 8; ++r) {
            s_bW1[a*S2 + h0 + r] = accB[r];
            s_dW1[a*S2 + h0 + r] = accD[r];
        }
    }
    __syncthreads();

    // ---- final: per (a,c) pair: h = leaky(baseW1[a] + w*diffW1[c]); out = h@W2 ----
    #pragma unroll
    for (int rep = 0; rep < 4; ++rep) {
        int idx = rep * 256 + tid;            // 0..1023
        int a = idx >> 5, c = idx & 31;
        float w = s_w[a*NA + c];
        float acc[8];
        #pragma unroll
        for (int o = 0; o < 8; ++o) acc[o] = 0.f;
        #pragma unroll 2
        for (int h = 0; h < DH; ++h) {
            float x = fmaf(w, s_dW1[c*S2 + h], s_bW1[a*S2 + h]);
            x = fmaxf(x, 0.01f * x);          // leaky_relu(0.01)
            float4 w2a = *reinterpret_cast<const float4*>(&s_W2[h*DO]);
            float4 w2b = *reinterpret_cast<const float4*>(&s_W2[h*DO + 4]);
            acc[0] = fmaf(x, w2a.x, acc[0]);
            acc[1] = fmaf(x, w2a.y, acc[1]);
            acc[2] = fmaf(x, w2a.z, acc[2]);
            acc[3] = fmaf(x, w2a.w, acc[3]);
            acc[4] = fmaf(x, w2b.x, acc[4]);
            acc[5] = fmaf(x, w2b.y, acc[5]);
            acc[6] = fmaf(x, w2b.z, acc[6]);
            acc[7] = fmaf(x, w2b.w, acc[7]);
        }
        float4* outp = reinterpret_cast<float4*>(
            value_out + (((size_t)b*NA + a)*NA + c) * DO);
        outp[0] = make_float4(acc[0], acc[1], acc[2], acc[3]);
        outp[1] = make_float4(acc[4], acc[5], acc[6], acc[7]);
    }
}

extern "C" void kernel_launch(void* const* d_in, const int* in_sizes, int n_in,
                              void* d_out, int out_size) {
    const float* states   = (const float*)d_in[0];
    const float* policies = (const float*)d_in[1];
    const float* actions  = (const float*)d_in[2];
    const float* Wk       = (const float*)d_in[3];
    const float* Wq       = (const float*)d_in[4];
    const float* Wv       = (const float*)d_in[5];
    const float* W1       = (const float*)d_in[6];
    const float* W2       = (const float*)d_in[7];

    float* value_out  = (float*)d_out;                                   // [B,N,N,8]
    float* weight_out = value_out + (size_t)BATCH * NA * NA * DO;        // [B,N,N]

    cudaFuncSetAttribute(critic_kernel,
                         cudaFuncAttributeMaxDynamicSharedMemorySize, SMEM_BYTES);
    critic_kernel<<<BATCH, 256, SMEM_BYTES>>>(
        states, policies, actions, Wk, Wq, Wv, W1, W2, value_out, weight_out);
}

// round 3
// speedup vs baseline: 1.4652x; 1.4652x over previous
#include <cuda_runtime.h>
#include <math.h>

#define BATCH 256
#define NA    32
#define OBS   128
#define ACT   8
#define DV    128
#define DH    64
#define DO    8
#define S1    132   // padded stride (floats) for 128-wide rows, float4-aligned
#define S2    68    // padded stride for 64-wide rows, float4-aligned

// ---- SMEM layout (floats) ----
#define OFF_STATES 0
#define OFF_T      (OFF_STATES + NA*S1)   // states @ M
#define OFF_AVA    (OFF_T + NA*S1)
#define OFF_DIFF   (OFF_AVA + NA*S1)
#define OFF_W      (OFF_DIFF + NA*S1)     // scores -> softmax weights [32][32]
#define OFF_AW1    (OFF_W + NA*NA)        // avA @ W1  [32][S2]
#define OFF_DW1    (OFF_AW1 + NA*S2)      // diff @ W1
#define OFF_BW1    (OFF_DW1 + NA*S2)      // w @ aW1
#define OFF_ACT    (OFF_BW1 + NA*S2)
#define OFF_POL    (OFF_ACT + NA*ACT)
#define OFF_W2     (OFF_POL + NA*ACT)
#define SMEM_FLOATS (OFF_W2 + DH*DO)
#define SMEM_BYTES  (SMEM_FLOATS * 4)

__device__ float g_M[OBS * OBS];   // Wq @ Wk^T (contract over DK), precomputed

// ---------------------------------------------------------------------------
// Helper: M[i][j] = sum_d Wq[i][d] * Wk[j][d]   (contract over the DK axis!)
// Wq, Wk are [OBS, DK] row-major. 64 blocks x 256 thr, each block 16x16 tile.
// ---------------------------------------------------------------------------
__global__ void compute_M_kernel(const float* __restrict__ Wq,
                                 const float* __restrict__ Wk) {
    __shared__ float qs[16][OBS + 4];
    __shared__ float ks[16][OBS + 4];
    const int i0 = (blockIdx.x & 7) * 16;
    const int j0 = (blockIdx.x >> 3) * 16;
    const int tid = threadIdx.x;
    // 16 rows x 128 floats = 512 float4 per matrix; 256 threads -> 2 each
    for (int idx = tid; idx < 16 * 32; idx += 256) {
        int r = idx >> 5, d4 = (idx & 31) * 4;
        *reinterpret_cast<float4*>(&qs[r][d4]) =
            *reinterpret_cast<const float4*>(&Wq[(i0 + r) * OBS + d4]);
        *reinterpret_cast<float4*>(&ks[r][d4]) =
            *reinterpret_cast<const float4*>(&Wk[(j0 + r) * OBS + d4]);
    }
    __syncthreads();
    const int ti = tid >> 4, tj = tid & 15;
    float acc = 0.f;
    #pragma unroll 8
    for (int d = 0; d < OBS; ++d)
        acc = fmaf(qs[ti][d], ks[tj][d], acc);
    g_M[(i0 + ti) * OBS + j0 + tj] = acc;
}

// ---------------------------------------------------------------------------
// Main fused kernel: one CTA per batch element, 256 threads
// ---------------------------------------------------------------------------
__global__ __launch_bounds__(256, 2)
void critic_kernel(const float* __restrict__ states,
                   const float* __restrict__ policies,
                   const float* __restrict__ actions,
                   const float* __restrict__ Wv,
                   const float* __restrict__ W1,
                   const float* __restrict__ W2,
                   float* __restrict__ value_out,
                   float* __restrict__ weight_out)
{
    extern __shared__ float sm[];
    float* s_states = sm + OFF_STATES;
    float* s_t      = sm + OFF_T;
    float* s_avA    = sm + OFF_AVA;
    float* s_diff   = sm + OFF_DIFF;
    float* s_w      = sm + OFF_W;
    float* s_aW1    = sm + OFF_AW1;
    float* s_dW1    = sm + OFF_DW1;
    float* s_bW1    = sm + OFF_BW1;
    float* s_act    = sm + OFF_ACT;
    float* s_pol    = sm + OFF_POL;
    float* s_W2     = sm + OFF_W2;

    const int b   = blockIdx.x;
    const int tid = threadIdx.x;

    // ---- stage inputs ----
    {
        const float* st_b = states + (size_t)b * NA * OBS;
        for (int idx = tid; idx < NA * OBS / 4; idx += 256) {
            int i = idx >> 5, d4 = (idx & 31) * 4;
            *reinterpret_cast<float4*>(&s_states[i * S1 + d4]) =
                *reinterpret_cast<const float4*>(&st_b[i * OBS + d4]);
        }
        for (int idx = tid; idx < NA * ACT; idx += 256) {
            s_act[idx] = actions [(size_t)b * NA * ACT + idx];
            s_pol[idx] = policies[(size_t)b * NA * ACT + idx];
        }
        for (int idx = tid; idx < DH * DO; idx += 256) s_W2[idx] = W2[idx];
    }
    __syncthreads();

    // =========================================================================
    // Phase 1 (merged): t = states@M  AND  avA/diff = tanh(concat@Wv) paths
    // Thread tile: 4 rows x 4 cols. 256 thr = 8 rowgrp x 32 colgrp.
    // =========================================================================
    {
        const int r0 = (tid >> 5) * 4;
        const int c0 = (tid & 31) * 4;
        float4 accT[4], accV[4];
        #pragma unroll
        for (int r = 0; r < 4; ++r) {
            accT[r] = make_float4(0.f, 0.f, 0.f, 0.f);
            accV[r] = make_float4(0.f, 0.f, 0.f, 0.f);
        }
        for (int kk = 0; kk < OBS; kk += 4) {
            float4 sv[4];
            #pragma unroll
            for (int r = 0; r < 4; ++r)
                sv[r] = *reinterpret_cast<const float4*>(&s_states[(r0 + r) * S1 + kk]);
            #pragma unroll
            for (int t = 0; t < 4; ++t) {
                float4 mq = *reinterpret_cast<const float4*>(&g_M[(kk + t) * OBS + c0]);
                float4 wv = *reinterpret_cast<const float4*>(&Wv [(kk + t) * DV  + c0]);
                #pragma unroll
                for (int r = 0; r < 4; ++r) {
                    float s = reinterpret_cast<const float*>(&sv[r])[t];
                    accT[r].x = fmaf(s, mq.x, accT[r].x);
                    accT[r].y = fmaf(s, mq.y, accT[r].y);
                    accT[r].z = fmaf(s, mq.z, accT[r].z);
                    accT[r].w = fmaf(s, mq.w, accT[r].w);
                    accV[r].x = fmaf(s, wv.x, accV[r].x);
                    accV[r].y = fmaf(s, wv.y, accV[r].y);
                    accV[r].z = fmaf(s, wv.z, accV[r].z);
                    accV[r].w = fmaf(s, wv.w, accV[r].w);
                }
            }
        }
        // store t now to free registers
        #pragma unroll
        for (int r = 0; r < 4; ++r)
            *reinterpret_cast<float4*>(&s_t[(r0 + r) * S1 + c0]) = accT[r];

        // action/policy tail (8 extra K) on the shared states partial sum
        float4 accA[4], accP[4];
        #pragma unroll
        for (int r = 0; r < 4; ++r) { accA[r] = accV[r]; accP[r] = accV[r]; }
        #pragma unroll
        for (int kk = 0; kk < ACT; ++kk) {
            float4 wv = *reinterpret_cast<const float4*>(&Wv[(OBS + kk) * DV + c0]);
            #pragma unroll
            for (int r = 0; r < 4; ++r) {
                float a = s_act[(r0 + r) * ACT + kk];
                float p = s_pol[(r0 + r) * ACT + kk];
                accA[r].x = fmaf(a, wv.x, accA[r].x);
                accA[r].y = fmaf(a, wv.y, accA[r].y);
                accA[r].z = fmaf(a, wv.z, accA[r].z);
                accA[r].w = fmaf(a, wv.w, accA[r].w);
                accP[r].x = fmaf(p, wv.x, accP[r].x);
                accP[r].y = fmaf(p, wv.y, accP[r].y);
                accP[r].z = fmaf(p, wv.z, accP[r].z);
                accP[r].w = fmaf(p, wv.w, accP[r].w);
            }
        }
        #pragma unroll
        for (int r = 0; r < 4; ++r) {
            float4 tA, dF;
            tA.x = tanhf(accA[r].x); tA.y = tanhf(accA[r].y);
            tA.z = tanhf(accA[r].z); tA.w = tanhf(accA[r].w);
            dF.x = tanhf(accP[r].x) - tA.x; dF.y = tanhf(accP[r].y) - tA.y;
            dF.z = tanhf(accP[r].z) - tA.z; dF.w = tanhf(accP[r].w) - tA.w;
            *reinterpret_cast<float4*>(&s_avA [(r0 + r) * S1 + c0]) = tA;
            *reinterpret_cast<float4*>(&s_diff[(r0 + r) * S1 + c0]) = dF;
        }
    }
    __syncthreads();

    // =========================================================================
    // Phase 2a: score[i][j] = (t[i,:] . states[j,:]) / sqrt(128)
    // =========================================================================
    {
        const int i0 = (tid >> 4) * 2;
        const int j0 = (tid & 15) * 2;
        float a00 = 0.f, a01 = 0.f, a10 = 0.f, a11 = 0.f;
        for (int kk = 0; kk < OBS; kk += 4) {
            float4 q0 = *reinterpret_cast<const float4*>(&s_t[i0 * S1 + kk]);
            float4 q1 = *reinterpret_cast<const float4*>(&s_t[(i0 + 1) * S1 + kk]);
            float4 k0 = *reinterpret_cast<const float4*>(&s_states[j0 * S1 + kk]);
            float4 k1 = *reinterpret_cast<const float4*>(&s_states[(j0 + 1) * S1 + kk]);
            a00 = fmaf(q0.x, k0.x, fmaf(q0.y, k0.y, fmaf(q0.z, k0.z, fmaf(q0.w, k0.w, a00))));
            a01 = fmaf(q0.x, k1.x, fmaf(q0.y, k1.y, fmaf(q0.z, k1.z, fmaf(q0.w, k1.w, a01))));
            a10 = fmaf(q1.x, k0.x, fmaf(q1.y, k0.y, fmaf(q1.z, k0.z, fmaf(q1.w, k0.w, a10))));
            a11 = fmaf(q1.x, k1.x, fmaf(q1.y, k1.y, fmaf(q1.z, k1.z, fmaf(q1.w, k1.w, a11))));
        }
        const float sc = 0.08838834764831845f;  // 1/sqrt(128)
        s_w[i0 * NA + j0]           = a00 * sc;
        s_w[i0 * NA + j0 + 1]       = a01 * sc;
        s_w[(i0 + 1) * NA + j0]     = a10 * sc;
        s_w[(i0 + 1) * NA + j0 + 1] = a11 * sc;
    }

    // =========================================================================
    // Phase 2b (same phase, independent data): aW1 = avA@W1, dW1 = diff@W1
    // =========================================================================
    {
        const int j0 = (tid >> 4) * 2;
        const int h0 = (tid & 15) * 4;
        float4 aA0 = make_float4(0,0,0,0), aA1 = make_float4(0,0,0,0);
        float4 aD0 = make_float4(0,0,0,0), aD1 = make_float4(0,0,0,0);
        for (int d = 0; d < DV; d += 4) {
            float4 av0 = *reinterpret_cast<const float4*>(&s_avA [ j0      * S1 + d]);
            float4 av1 = *reinterpret_cast<const float4*>(&s_avA [(j0 + 1) * S1 + d]);
            float4 df0 = *reinterpret_cast<const float4*>(&s_diff[ j0      * S1 + d]);
            float4 df1 = *reinterpret_cast<const float4*>(&s_diff[(j0 + 1) * S1 + d]);
            #pragma unroll
            for (int t = 0; t < 4; ++t) {
                float4 w1 = *reinterpret_cast<const float4*>(&W1[(d + t) * DH + h0]);
                float a0 = reinterpret_cast<const float*>(&av0)[t];
                float a1 = reinterpret_cast<const float*>(&av1)[t];
                float d0 = reinterpret_cast<const float*>(&df0)[t];
                float d1 = reinterpret_cast<const float*>(&df1)[t];
                aA0.x = fmaf(a0, w1.x, aA0.x); aA0.y = fmaf(a0, w1.y, aA0.y);
                aA0.z = fmaf(a0, w1.z, aA0.z); aA0.w = fmaf(a0, w1.w, aA0.w);
                aA1.x = fmaf(a1, w1.x, aA1.x); aA1.y = fmaf(a1, w1.y, aA1.y);
                aA1.z = fmaf(a1, w1.z, aA1.z); aA1.w = fmaf(a1, w1.w, aA1.w);
                aD0.x = fmaf(d0, w1.x, aD0.x); aD0.y = fmaf(d0, w1.y, aD0.y);
                aD0.z = fmaf(d0, w1.z, aD0.z); aD0.w = fmaf(d0, w1.w, aD0.w);
                aD1.x = fmaf(d1, w1.x, aD1.x); aD1.y = fmaf(d1, w1.y, aD1.y);
                aD1.z = fmaf(d1, w1.z, aD1.z); aD1.w = fmaf(d1, w1.w, aD1.w);
            }
        }
        *reinterpret_cast<float4*>(&s_aW1[ j0      * S2 + h0]) = aA0;
        *reinterpret_cast<float4*>(&s_aW1[(j0 + 1) * S2 + h0]) = aA1;
        *reinterpret_cast<float4*>(&s_dW1[ j0      * S2 + h0]) = aD0;
        *reinterpret_cast<float4*>(&s_dW1[(j0 + 1) * S2 + h0]) = aD1;
    }
    __syncthreads();

    // =========================================================================
    // Phase 3: softmax over j — one warp per row (8 warps x 4 rows)
    // =========================================================================
    {
        const int warp = tid >> 5, lane = tid & 31;
        #pragma unroll
        for (int rr = 0; rr < 4; ++rr) {
            const int row = warp * 4 + rr;
            float v = s_w[row * NA + lane];
            float m = v;
            #pragma unroll
            for (int off = 16; off > 0; off >>= 1)
                m = fmaxf(m, __shfl_xor_sync(0xffffffffu, m, off));
            float e = expf(v - m);
            float s = e;
            #pragma unroll
            for (int off = 16; off > 0; off >>= 1)
                s += __shfl_xor_sync(0xffffffffu, s, off);
            float w = e / s;
            s_w[row * NA + lane] = w;
            weight_out[(size_t)b * NA * NA + row * NA + lane] = w;
        }
    }
    __syncthreads();

    // =========================================================================
    // Phase 4: bW1 = w @ aW1   [32 x 64]
    // =========================================================================
    {
        const int a0 = (tid >> 4) * 2;
        const int h0 = (tid & 15) * 4;
        float4 acc0 = make_float4(0,0,0,0), acc1 = make_float4(0,0,0,0);
        for (int j = 0; j < NA; j += 4) {
            float4 w0 = *reinterpret_cast<const float4*>(&s_w[ a0      * NA + j]);
            float4 w1 = *reinterpret_cast<const float4*>(&s_w[(a0 + 1) * NA + j]);
            #pragma unroll
            for (int t = 0; t < 4; ++t) {
                float4 aw = *reinterpret_cast<const float4*>(&s_aW1[(j + t) * S2 + h0]);
                float v0 = reinterpret_cast<const float*>(&w0)[t];
                float v1 = reinterpret_cast<const float*>(&w1)[t];
                acc0.x = fmaf(v0, aw.x, acc0.x); acc0.y = fmaf(v0, aw.y, acc0.y);
                acc0.z = fmaf(v0, aw.z, acc0.z); acc0.w = fmaf(v0, aw.w, acc0.w);
                acc1.x = fmaf(v1, aw.x, acc1.x); acc1.y = fmaf(v1, aw.y, acc1.y);
                acc1.z = fmaf(v1, aw.z, acc1.z); acc1.w = fmaf(v1, aw.w, acc1.w);
            }
        }
        *reinterpret_cast<float4*>(&s_bW1[ a0      * S2 + h0]) = acc0;
        *reinterpret_cast<float4*>(&s_bW1[(a0 + 1) * S2 + h0]) = acc1;
    }
    __syncthreads();

    // =========================================================================
    // Phase 5: final. Each thread handles 4 pairs (a0+8k, c) so W2/dW1 loads
    // amortize. h = leaky(bW1[a] + w*dW1[c]); out = h @ W2.
    // =========================================================================
    {
        const int a0 = tid >> 5;      // 0..7
        const int c  = tid & 31;      // 0..31
        float wk[4];
        #pragma unroll
        for (int k = 0; k < 4; ++k) wk[k] = s_w[(a0 + 8 * k) * NA + c];

        float4 accL[4], accH[4];
        #pragma unroll
        for (int k = 0; k < 4; ++k) {
            accL[k] = make_float4(0,0,0,0);
            accH[k] = make_float4(0,0,0,0);
        }
        for (int h = 0; h < DH; h += 4) {
            float4 dq = *reinterpret_cast<const float4*>(&s_dW1[c * S2 + h]);
            float4 w2lo[4], w2hi[4];
            #pragma unroll
            for (int t = 0; t < 4; ++t) {
                w2lo[t] = *reinterpret_cast<const float4*>(&s_W2[(h + t) * DO]);
                w2hi[t] = *reinterpret_cast<const float4*>(&s_W2[(h + t) * DO + 4]);
            }
            #pragma unroll
            for (int k = 0; k < 4; ++k) {
                float4 bq = *reinterpret_cast<const float4*>(&s_bW1[(a0 + 8 * k) * S2 + h]);
                #pragma unroll
                for (int t = 0; t < 4; ++t) {
                    float x = fmaf(wk[k],
                                   reinterpret_cast<const float*>(&dq)[t],
                                   reinterpret_cast<const float*>(&bq)[t]);
                    x = fmaxf(x, 0.01f * x);   // leaky_relu(0.01)
                    accL[k].x = fmaf(x, w2lo[t].x, accL[k].x);
                    accL[k].y = fmaf(x, w2lo[t].y, accL[k].y);
                    accL[k].z = fmaf(x, w2lo[t].z, accL[k].z);
                    accL[k].w = fmaf(x, w2lo[t].w, accL[k].w);
                    accH[k].x = fmaf(x, w2hi[t].x, accH[k].x);
                    accH[k].y = fmaf(x, w2hi[t].y, accH[k].y);
                    accH[k].z = fmaf(x, w2hi[t].z, accH[k].z);
                    accH[k].w = fmaf(x, w2hi[t].w, accH[k].w);
                }
            }
        }
        #pragma unroll
        for (int k = 0; k < 4; ++k) {
            float4* outp = reinterpret_cast<float4*>(
                value_out + (((size_t)b * NA + (a0 + 8 * k)) * NA + c) * DO);
            outp[0] = accL[k];
            outp[1] = accH[k];
        }
    }
}

extern "C" void kernel_launch(void* const* d_in, const int* in_sizes, int n_in,
                              void* d_out, int out_size) {
    const float* states   = (const float*)d_in[0];
    const float* policies = (const float*)d_in[1];
    const float* actions  = (const float*)d_in[2];
    const float* Wk       = (const float*)d_in[3];
    const float* Wq       = (const float*)d_in[4];
    const float* Wv       = (const float*)d_in[5];
    const float* W1       = (const float*)d_in[6];
    const float* W2       = (const float*)d_in[7];

    float* value_out  = (float*)d_out;                              // [B,N,N,8]
    float* weight_out = value_out + (size_t)BATCH * NA * NA * DO;   // [B,N,N]

    compute_M_kernel<<<64, 256>>>(Wq, Wk);

    cudaFuncSetAttribute(critic_kernel,
                         cudaFuncAttributeMaxDynamicSharedMemorySize, SMEM_BYTES);
    critic_kernel<<<BATCH, 256, SMEM_BYTES>>>(
        states, policies, actions, Wv, W1, W2, value_out, weight_out);
}